// round 1
// baseline (speedup 1.0000x reference)
#include <cuda_runtime.h>
#include <math_constants.h>

#define B_ 2
#define T_ 192
#define C_ 512
#define H_ 8
#define HS_ 64
#define ORDER_ 3
#define BH_ (B_*H_)

#define JB_ 32
#define NJB_ (T_/JB_)
#define ITILE_ 2

// ---- device scratch (allocation-free rule: __device__ globals) ----
__device__ float g_Q [BH_*T_*HS_];
__device__ float g_K1[BH_*T_*HS_];
__device__ float g_K2[BH_*T_*HS_];
__device__ float g_V1[BH_*T_*HS_];
__device__ float g_V2[BH_*T_*HS_];
__device__ float g_Y [B_*T_*C_];

__device__ __forceinline__ float warpMax(float v) {
#pragma unroll
    for (int o = 16; o; o >>= 1) v = fmaxf(v, __shfl_xor_sync(0xffffffffu, v, o));
    return v;
}
__device__ __forceinline__ float warpSum(float v) {
#pragma unroll
    for (int o = 16; o; o >>= 1) v += __shfl_xor_sync(0xffffffffu, v, o);
    return v;
}

// =====================================================================
// Kernel 1: 5 per-head projections  out[b,h,t,d] = sum_c x[b,t,c]*w[h,o,d,c] + bias
// grid (T/16, BH, 5), block 256
// =====================================================================
__global__ void proj_kernel(const float* __restrict__ x0, const float* __restrict__ x1,
                            const float* __restrict__ x2,
                            const float* __restrict__ qw, const float* __restrict__ qb,
                            const float* __restrict__ kw, const float* __restrict__ kb,
                            const float* __restrict__ vw, const float* __restrict__ vb)
{
    __shared__ float xs[16][64];
    __shared__ float ws[64][65];   // pad 65 -> conflict-free ws[d][c] with d=lane

    int m  = blockIdx.z;
    int bh = blockIdx.y;
    int b  = bh / H_, h = bh % H_;
    int t0 = blockIdx.x * 16;

    const float* x; const float* w; const float* bias; float* out; int o;
    switch (m) {
        case 0:  x = x0; w = qw; bias = qb; out = g_Q;  o = 0; break;
        case 1:  x = x1; w = kw; bias = kb; out = g_K1; o = 1; break;
        case 2:  x = x2; w = kw; bias = kb; out = g_K2; o = 2; break;
        case 3:  x = x1; w = vw; bias = vb; out = g_V1; o = 1; break;
        default: x = x2; w = vw; bias = vb; out = g_V2; o = 2; break;
    }
    const float* wrow = w + (size_t)(h*ORDER_ + o)*HS_*C_;
    const float* brow = bias + (h*ORDER_ + o)*HS_;

    int tid = threadIdx.x;
    int d   = tid & 63;
    int rb  = (tid >> 6) * 4;
    float acc[4] = {0.f, 0.f, 0.f, 0.f};

    for (int cc = 0; cc < C_; cc += 64) {
        for (int idx = tid; idx < 16*64; idx += 256) {
            int r = idx >> 6, c = idx & 63;
            xs[r][c] = x[(size_t)(b*T_ + t0 + r)*C_ + cc + c];
        }
        for (int idx = tid; idx < 64*64; idx += 256) {
            int dr = idx >> 6, c = idx & 63;
            ws[dr][c] = wrow[(size_t)dr*C_ + cc + c];
        }
        __syncthreads();
#pragma unroll
        for (int c = 0; c < 64; ++c) {
            float wv = ws[d][c];
            acc[0] = fmaf(xs[rb+0][c], wv, acc[0]);
            acc[1] = fmaf(xs[rb+1][c], wv, acc[1]);
            acc[2] = fmaf(xs[rb+2][c], wv, acc[2]);
            acc[3] = fmaf(xs[rb+3][c], wv, acc[3]);
        }
        __syncthreads();
    }
    float bv = brow[d];
#pragma unroll
    for (int rr = 0; rr < 4; ++rr)
        out[(size_t)(bh*T_ + t0 + rb + rr)*HS_ + d] = acc[rr] + bv;
}

// =====================================================================
// Kernel 2: order-3 attention with online softmax over flattened (j,k)
// grid (T/ITILE, BH), block 256, 1 CTA handles (b,h) x ITILE query rows
// =====================================================================
__global__ void __launch_bounds__(256, 1) attn_kernel()
{
    extern __shared__ float sm[];
    float* K1s = sm;                    // [192][64]
    float* K2s = K1s + 192*64;          // [192][65]  padded
    float* V1s = K2s + 192*65;          // [192][64]
    float* V2s = V1s + 192*64;          // [192][64]
    float* Sb  = V2s + 192*64;          // [32][192]  score / prob block
    float* qs  = Sb  + JB_*192;         // [64]
    float* red = qs + 64;               // [32] reduction slots (use 0..9)
    float* Ys  = red + 32;              // [256]

    int bh  = blockIdx.y;
    int it0 = blockIdx.x * ITILE_;
    int tid  = threadIdx.x;
    int lane = tid & 31, wid = tid >> 5;
    int jt = tid >> 6;      // 0..3
    int dd = tid & 63;      // k-offset in GEMM1, d in GEMM2
    int b = bh >> 3, h = bh & 7;

    const float* K1g = g_K1 + (size_t)bh*T_*HS_;
    const float* K2g = g_K2 + (size_t)bh*T_*HS_;
    const float* V1g = g_V1 + (size_t)bh*T_*HS_;
    const float* V2g = g_V2 + (size_t)bh*T_*HS_;

    // stage K/V tiles (192x64 each)
    for (int idx = tid; idx < 192*16; idx += 256) {
        int j = idx >> 4, d4 = idx & 15;
        ((float4*)K1s)[idx] = ((const float4*)K1g)[idx];
        float4 v2 = ((const float4*)K2g)[idx];
        int base = j*65 + d4*4;
        K2s[base+0] = v2.x; K2s[base+1] = v2.y; K2s[base+2] = v2.z; K2s[base+3] = v2.w;
        ((float4*)V1s)[idx] = ((const float4*)V1g)[idx];
        ((float4*)V2s)[idx] = ((const float4*)V2g)[idx];
    }
    __syncthreads();

    for (int ii = 0; ii < ITILE_; ++ii) {
        int i = it0 + ii;
        if (tid < 64) qs[tid] = g_Q[((size_t)bh*T_ + i)*HS_ + tid] * 0.125f; // fold 1/sqrt(64)
        __syncthreads();

        float m_run = -CUDART_INF_F, l_run = 0.f, yacc = 0.f;

        for (int jb = 0; jb < NJB_; ++jb) {
            int j0 = jb * JB_;
            // ---------------- GEMM1: S[j,k] = sum_d (K1[j,d]*q[d]) * K2[k,d] ----
            float s[8][3];
#pragma unroll
            for (int jj = 0; jj < 8; ++jj)
#pragma unroll
                for (int kk = 0; kk < 3; ++kk) s[jj][kk] = 0.f;

#pragma unroll 4
            for (int d = 0; d < 64; d += 4) {
                float4 q4 = *(const float4*)&qs[d];
                float b0[3], b1[3], b2[3], b3[3];
#pragma unroll
                for (int kk = 0; kk < 3; ++kk) {
                    const float* kp = &K2s[(dd + 64*kk)*65 + d];
                    b0[kk] = kp[0]*q4.x; b1[kk] = kp[1]*q4.y;
                    b2[kk] = kp[2]*q4.z; b3[kk] = kp[3]*q4.w;
                }
#pragma unroll
                for (int jj = 0; jj < 8; ++jj) {
                    float4 a = *(const float4*)&K1s[(j0 + jt + 4*jj)*64 + d];
#pragma unroll
                    for (int kk = 0; kk < 3; ++kk)
                        s[jj][kk] = fmaf(a.x, b0[kk],
                                    fmaf(a.y, b1[kk],
                                    fmaf(a.z, b2[kk],
                                    fmaf(a.w, b3[kk], s[jj][kk]))));
                }
            }

            // ---------------- block max ----------------
            float lmax = -CUDART_INF_F;
#pragma unroll
            for (int jj = 0; jj < 8; ++jj)
#pragma unroll
                for (int kk = 0; kk < 3; ++kk) lmax = fmaxf(lmax, s[jj][kk]);
            float wm = warpMax(lmax);
            if (lane == 0) red[wid] = wm;
            __syncthreads();
            if (tid == 0) {
                float mm = red[0];
#pragma unroll
                for (int w = 1; w < 8; ++w) mm = fmaxf(mm, red[w]);
                red[8] = mm;
            }
            __syncthreads();
            float m_new = fmaxf(m_run, red[8]);

            // ---------------- exp + write P + local sum ----------------
            float lsum = 0.f;
#pragma unroll
            for (int jj = 0; jj < 8; ++jj) {
                int row = (jt + 4*jj)*192;
#pragma unroll
                for (int kk = 0; kk < 3; ++kk) {
                    float p = __expf(s[jj][kk] - m_new);
                    lsum += p;
                    Sb[row + dd + 64*kk] = p;
                }
            }
            float wsum = warpSum(lsum);
            if (lane == 0) red[wid] = wsum;
            __syncthreads();
            if (tid == 0) {
                float ss = 0.f;
#pragma unroll
                for (int w = 0; w < 8; ++w) ss += red[w];
                red[9] = ss;
            }
            __syncthreads();
            float alpha = __expf(m_run - m_new);   // 0 on first block
            l_run = l_run * alpha + red[9];
            m_run = m_new;
            yacc *= alpha;

            // ---------------- GEMM2 + V1 reduce: yacc += V1[j,d]*(P[j,:]@V2)[d] --
#pragma unroll
            for (int jj = 0; jj < 8; ++jj) {
                int jl = jt + 4*jj;
                float acc = 0.f;
#pragma unroll 12
                for (int k = 0; k < 192; k += 4) {
                    float4 p = *(const float4*)&Sb[jl*192 + k];
                    acc = fmaf(p.x, V2s[(k+0)*64 + dd],
                          fmaf(p.y, V2s[(k+1)*64 + dd],
                          fmaf(p.z, V2s[(k+2)*64 + dd],
                          fmaf(p.w, V2s[(k+3)*64 + dd], acc))));
                }
                yacc = fmaf(V1s[(j0 + jl)*64 + dd], acc, yacc);
            }
            __syncthreads();   // Sb reused next block
        }

        // reduce yacc over the 4 jt groups for each d
        Ys[tid] = yacc;
        __syncthreads();
        if (jt == 0) {
            float y = (Ys[dd] + Ys[64 + dd] + Ys[128 + dd] + Ys[192 + dd]) / l_run;
            g_Y[((size_t)(b*T_ + i)*H_ + h)*HS_ + dd] = y;   // (B,T,H,HS) = (B,T,C)
        }
        __syncthreads();
    }
}

// =====================================================================
// Kernel 3: output projection  out = Y @ cw^T + cb   (384x512 @ 512x512)
// grid (48, 4), block 256
// =====================================================================
__global__ void outproj_kernel(const float* __restrict__ cw, const float* __restrict__ cb,
                               float* __restrict__ out)
{
    __shared__ float xs[8][64];
    __shared__ float ws[128][65];

    int r0  = blockIdx.x * 8;
    int co0 = blockIdx.y * 128;
    int tid = threadIdx.x;
    int col = tid & 127;
    int rb  = (tid >> 7) * 4;
    float acc[4] = {0.f, 0.f, 0.f, 0.f};

    for (int cc = 0; cc < C_; cc += 64) {
        for (int idx = tid; idx < 8*64; idx += 256) {
            int r = idx >> 6, c = idx & 63;
            xs[r][c] = g_Y[(size_t)(r0 + r)*C_ + cc + c];
        }
        for (int idx = tid; idx < 128*64; idx += 256) {
            int dr = idx >> 6, c = idx & 63;
            ws[dr][c] = cw[(size_t)(co0 + dr)*C_ + cc + c];
        }
        __syncthreads();
#pragma unroll
        for (int c = 0; c < 64; ++c) {
            float wv = ws[col][c];
            acc[0] = fmaf(xs[rb+0][c], wv, acc[0]);
            acc[1] = fmaf(xs[rb+1][c], wv, acc[1]);
            acc[2] = fmaf(xs[rb+2][c], wv, acc[2]);
            acc[3] = fmaf(xs[rb+3][c], wv, acc[3]);
        }
        __syncthreads();
    }
    float bv = cb[co0 + col];
#pragma unroll
    for (int rr = 0; rr < 4; ++rr)
        out[(size_t)(r0 + rb + rr)*C_ + co0 + col] = acc[rr] + bv;
}

// =====================================================================
extern "C" void kernel_launch(void* const* d_in, const int* in_sizes, int n_in,
                              void* d_out, int out_size)
{
    const float* x0 = (const float*)d_in[0];
    const float* x1 = (const float*)d_in[1];
    const float* x2 = (const float*)d_in[2];
    const float* qw = (const float*)d_in[3];
    const float* qb = (const float*)d_in[4];
    const float* kw = (const float*)d_in[5];
    const float* kb = (const float*)d_in[6];
    const float* vw = (const float*)d_in[7];
    const float* vb = (const float*)d_in[8];
    const float* cw = (const float*)d_in[9];
    const float* cb = (const float*)d_in[10];
    float* out = (float*)d_out;

    proj_kernel<<<dim3(T_/16, BH_, 5), 256>>>(x0, x1, x2, qw, qb, kw, kb, vw, vb);

    size_t smem = (size_t)(192*64 + 192*65 + 192*64 + 192*64 + JB_*192 + 64 + 32 + 256) * sizeof(float);
    cudaFuncSetAttribute(attn_kernel, cudaFuncAttributeMaxDynamicSharedMemorySize, (int)smem);
    attn_kernel<<<dim3(T_/ITILE_, BH_), 256, smem>>>();

    outproj_kernel<<<dim3((B_*T_)/8, C_/128), 256>>>(cw, cb, out);
}

// round 2
// speedup vs baseline: 1.6012x; 1.6012x over previous
#include <cuda_runtime.h>
#include <math_constants.h>

#define B_ 2
#define T_ 192
#define C_ 512
#define H_ 8
#define HS_ 64
#define ORDER_ 3
#define BH_ (B_*H_)

#define JB_ 32
#define NJB_ (T_/JB_)
#define ITILE_ 4

// smem float offsets (attn kernel)
#define OFF_K1  0
#define OFF_K2  12288              // 192*64
#define OFF_V1  25344              // +192*68
#define OFF_V2T 37632              // +192*64
#define OFF_SB  50176              // +64*196
#define OFF_QS  56320              // +32*192
#define OFF_RED 56384
#define OFF_YS  56400
#define SMEM_FLOATS 56656

// ---- device scratch (allocation-free rule: __device__ globals) ----
__device__ float g_Q [BH_*T_*HS_];
__device__ float g_K1[BH_*T_*HS_];
__device__ float g_K2[BH_*T_*HS_];
__device__ float g_V1[BH_*T_*HS_];
__device__ float g_V2[BH_*T_*HS_];
__device__ float g_Y [B_*T_*C_];

// ---- packed fp32x2 helpers (Blackwell dual-FP32 pipe, PTX-only pattern) ----
typedef unsigned long long u64;

__device__ __forceinline__ u64 ffma2(u64 a, u64 b, u64 c) {
    u64 d;
    asm("fma.rn.f32x2 %0, %1, %2, %3;" : "=l"(d) : "l"(a), "l"(b), "l"(c));
    return d;
}
__device__ __forceinline__ u64 fmul2(u64 a, u64 b) {
    u64 d;
    asm("mul.rn.f32x2 %0, %1, %2;" : "=l"(d) : "l"(a), "l"(b));
    return d;
}
__device__ __forceinline__ float pk_sum(u64 v) {
    float lo = __uint_as_float((unsigned int)(v & 0xffffffffull));
    float hi = __uint_as_float((unsigned int)(v >> 32));
    return lo + hi;
}

__device__ __forceinline__ float warpMax(float v) {
#pragma unroll
    for (int o = 16; o; o >>= 1) v = fmaxf(v, __shfl_xor_sync(0xffffffffu, v, o));
    return v;
}
__device__ __forceinline__ float warpSum(float v) {
#pragma unroll
    for (int o = 16; o; o >>= 1) v += __shfl_xor_sync(0xffffffffu, v, o);
    return v;
}

// =====================================================================
// Kernel 1: 5 per-head projections  out[b,h,t,d] = sum_c x[b,t,c]*w[h,o,d,c] + b
// grid (T/48, BH, 5), block 256
// =====================================================================
__global__ void proj_kernel(const float* __restrict__ x0, const float* __restrict__ x1,
                            const float* __restrict__ x2,
                            const float* __restrict__ qw, const float* __restrict__ qb,
                            const float* __restrict__ kw, const float* __restrict__ kb,
                            const float* __restrict__ vw, const float* __restrict__ vb)
{
    __shared__ float xs[48][64];
    __shared__ float ws[64][65];

    int m  = blockIdx.z;
    int bh = blockIdx.y;
    int b  = bh / H_, h = bh % H_;
    int t0 = blockIdx.x * 48;

    const float* x; const float* w; const float* bias; float* out; int o;
    switch (m) {
        case 0:  x = x0; w = qw; bias = qb; out = g_Q;  o = 0; break;
        case 1:  x = x1; w = kw; bias = kb; out = g_K1; o = 1; break;
        case 2:  x = x2; w = kw; bias = kb; out = g_K2; o = 2; break;
        case 3:  x = x1; w = vw; bias = vb; out = g_V1; o = 1; break;
        default: x = x2; w = vw; bias = vb; out = g_V2; o = 2; break;
    }
    const float* wrow = w + (size_t)(h*ORDER_ + o)*HS_*C_;
    const float* brow = bias + (h*ORDER_ + o)*HS_;

    int tid = threadIdx.x;
    int d   = tid & 63;
    int rb  = (tid >> 6) * 12;
    float acc[12];
#pragma unroll
    for (int r = 0; r < 12; ++r) acc[r] = 0.f;

    for (int cc = 0; cc < C_; cc += 64) {
        for (int idx = tid; idx < 48*64; idx += 256) {
            int r = idx >> 6, c = idx & 63;
            xs[r][c] = x[(size_t)(b*T_ + t0 + r)*C_ + cc + c];
        }
        for (int idx = tid; idx < 64*64; idx += 256) {
            int dr = idx >> 6, c = idx & 63;
            ws[dr][c] = wrow[(size_t)dr*C_ + cc + c];
        }
        __syncthreads();
#pragma unroll 16
        for (int c = 0; c < 64; ++c) {
            float wv = ws[d][c];
#pragma unroll
            for (int r = 0; r < 12; ++r)
                acc[r] = fmaf(xs[rb+r][c], wv, acc[r]);
        }
        __syncthreads();
    }
    float bv = brow[d];
#pragma unroll
    for (int r = 0; r < 12; ++r)
        out[(size_t)(bh*T_ + t0 + rb + r)*HS_ + d] = acc[r] + bv;
}

// =====================================================================
// Kernel 2: order-3 attention, online softmax over flattened (j,k)
// grid (T/ITILE, BH), block 256, f32x2 packed math
// =====================================================================
__global__ void __launch_bounds__(256, 1) attn_kernel()
{
    extern __shared__ float sm[];
    float* K1s = sm + OFF_K1;    // [192][64]
    float* K2s = sm + OFF_K2;    // [192][68]  padded (quad-aligned, phase-conflict-free)
    float* V1s = sm + OFF_V1;    // [192][64]
    float* V2t = sm + OFF_V2T;   // [64][196]  transposed V2, padded
    float* Sb  = sm + OFF_SB;    // [32][192]
    float* qs  = sm + OFF_QS;    // [64]
    float* red = sm + OFF_RED;   // [16]
    float* Ys  = sm + OFF_YS;    // [256]

    int bh  = blockIdx.y;
    int it0 = blockIdx.x * ITILE_;
    int tid  = threadIdx.x;
    int lane = tid & 31, wid = tid >> 5;
    int jt = tid >> 6;      // 0..3
    int dd = tid & 63;      // 0..63
    int b = bh >> 3, h = bh & 7;

    const float* K1g = g_K1 + (size_t)bh*T_*HS_;
    const float* K2g = g_K2 + (size_t)bh*T_*HS_;
    const float* V1g = g_V1 + (size_t)bh*T_*HS_;
    const float* V2g = g_V2 + (size_t)bh*T_*HS_;

    // ---- stage K/V tiles ----
    for (int idx = tid; idx < 192*16; idx += 256) {
        int j = idx >> 4, d4 = idx & 15;
        ((float4*)K1s)[idx] = ((const float4*)K1g)[idx];
        ((float4*)V1s)[idx] = ((const float4*)V1g)[idx];
        float4 k2 = ((const float4*)K2g)[idx];
        int kb = j*68 + d4*4;
        K2s[kb+0] = k2.x; K2s[kb+1] = k2.y; K2s[kb+2] = k2.z; K2s[kb+3] = k2.w;
        float4 v2 = ((const float4*)V2g)[idx];
        int dv = d4*4;
        V2t[(dv+0)*196 + j] = v2.x;
        V2t[(dv+1)*196 + j] = v2.y;
        V2t[(dv+2)*196 + j] = v2.z;
        V2t[(dv+3)*196 + j] = v2.w;
    }
    __syncthreads();

    for (int ii = 0; ii < ITILE_; ++ii) {
        int i = it0 + ii;
        if (tid < 64) qs[tid] = g_Q[((size_t)bh*T_ + i)*HS_ + tid] * 0.125f; // fold 1/sqrt(64)
        __syncthreads();

        float m_run = -CUDART_INF_F, l_run = 0.f, yacc = 0.f;

        for (int jb = 0; jb < NJB_; ++jb) {
            int j0 = jb * JB_;

            // ---------- GEMM1: S[j,k] = sum_d K1[j,d]*(q[d]*K2[k,d]) ----------
            u64 acc2[8][3];
#pragma unroll
            for (int jj = 0; jj < 8; ++jj)
#pragma unroll
                for (int kk = 0; kk < 3; ++kk) acc2[jj][kk] = 0ull;

#pragma unroll 4
            for (int d = 0; d < 64; d += 4) {
                ulonglong2 q2 = *(const ulonglong2*)&qs[d];
                u64 bq[3][2];
#pragma unroll
                for (int kk = 0; kk < 3; ++kk) {
                    ulonglong2 k2 = *(const ulonglong2*)&K2s[(dd + 64*kk)*68 + d];
                    bq[kk][0] = fmul2(k2.x, q2.x);
                    bq[kk][1] = fmul2(k2.y, q2.y);
                }
#pragma unroll
                for (int jj = 0; jj < 8; ++jj) {
                    ulonglong2 a2 = *(const ulonglong2*)&K1s[(j0 + jt + 4*jj)*64 + d];
#pragma unroll
                    for (int kk = 0; kk < 3; ++kk)
                        acc2[jj][kk] = ffma2(a2.x, bq[kk][0],
                                       ffma2(a2.y, bq[kk][1], acc2[jj][kk]));
                }
            }
            float s[8][3];
            float lmax = -CUDART_INF_F;
#pragma unroll
            for (int jj = 0; jj < 8; ++jj)
#pragma unroll
                for (int kk = 0; kk < 3; ++kk) {
                    s[jj][kk] = pk_sum(acc2[jj][kk]);
                    lmax = fmaxf(lmax, s[jj][kk]);
                }

            // ---------- block max ----------
            float wm = warpMax(lmax);
            if (lane == 0) red[wid] = wm;
            __syncthreads();
            float mm = red[0];
#pragma unroll
            for (int w = 1; w < 8; ++w) mm = fmaxf(mm, red[w]);
            float m_new = fmaxf(m_run, mm);
            float alpha = __expf(m_run - m_new);   // 0 on first block

            // ---------- exp + write P + deferred local sum ----------
            float lsum = 0.f;
#pragma unroll
            for (int jj = 0; jj < 8; ++jj) {
                int row = (jt + 4*jj)*192;
#pragma unroll
                for (int kk = 0; kk < 3; ++kk) {
                    float p = __expf(s[jj][kk] - m_new);
                    lsum += p;
                    Sb[row + dd + 64*kk] = p;
                }
            }
            l_run = l_run * alpha + lsum;
            m_run = m_new;
            yacc *= alpha;
            __syncthreads();   // Sb visible to all

            // ---------- GEMM2: yacc += V1[j,dd] * sum_k P[j,k]*V2[k,dd] ----------
            u64 w2[8];
#pragma unroll
            for (int jj = 0; jj < 8; ++jj) w2[jj] = 0ull;

#pragma unroll 4
            for (int k = 0; k < 192; k += 4) {
                ulonglong2 v2 = *(const ulonglong2*)&V2t[dd*196 + k];
#pragma unroll
                for (int jj = 0; jj < 8; ++jj) {
                    ulonglong2 p2 = *(const ulonglong2*)&Sb[(jt + 4*jj)*192 + k];
                    w2[jj] = ffma2(p2.x, v2.x, ffma2(p2.y, v2.y, w2[jj]));
                }
            }
#pragma unroll
            for (int jj = 0; jj < 8; ++jj)
                yacc = fmaf(V1s[(j0 + jt + 4*jj)*64 + dd], pk_sum(w2[jj]), yacc);

            __syncthreads();   // Sb / red reused next strip
        }

        // ---- per-query reductions: y over jt groups, l over all threads ----
        Ys[tid] = yacc;
        float lw = warpSum(l_run);
        if (lane == 0) red[wid] = lw;
        __syncthreads();
        float l_tot = red[0];
#pragma unroll
        for (int w = 1; w < 8; ++w) l_tot += red[w];
        if (jt == 0) {
            float y = (Ys[dd] + Ys[64 + dd] + Ys[128 + dd] + Ys[192 + dd]) / l_tot;
            g_Y[((size_t)(b*T_ + i)*H_ + h)*HS_ + dd] = y;   // (B,T,H,HS)
        }
        __syncthreads();
    }
}

// =====================================================================
// Kernel 3: output projection  out = Y @ cw^T + cb   (384x512 @ 512x512)
// =====================================================================
__global__ void outproj_kernel(const float* __restrict__ cw, const float* __restrict__ cb,
                               float* __restrict__ out)
{
    __shared__ float xs[8][64];
    __shared__ float ws[128][65];

    int r0  = blockIdx.x * 8;
    int co0 = blockIdx.y * 128;
    int tid = threadIdx.x;
    int col = tid & 127;
    int rb  = (tid >> 7) * 4;
    float acc[4] = {0.f, 0.f, 0.f, 0.f};

    for (int cc = 0; cc < C_; cc += 64) {
        for (int idx = tid; idx < 8*64; idx += 256) {
            int r = idx >> 6, c = idx & 63;
            xs[r][c] = g_Y[(size_t)(r0 + r)*C_ + cc + c];
        }
        for (int idx = tid; idx < 128*64; idx += 256) {
            int dr = idx >> 6, c = idx & 63;
            ws[dr][c] = cw[(size_t)(co0 + dr)*C_ + cc + c];
        }
        __syncthreads();
#pragma unroll
        for (int c = 0; c < 64; ++c) {
            float wv = ws[col][c];
            acc[0] = fmaf(xs[rb+0][c], wv, acc[0]);
            acc[1] = fmaf(xs[rb+1][c], wv, acc[1]);
            acc[2] = fmaf(xs[rb+2][c], wv, acc[2]);
            acc[3] = fmaf(xs[rb+3][c], wv, acc[3]);
        }
        __syncthreads();
    }
    float bv = cb[co0 + col];
#pragma unroll
    for (int rr = 0; rr < 4; ++rr)
        out[(size_t)(r0 + rb + rr)*C_ + co0 + col] = acc[rr] + bv;
}

// =====================================================================
extern "C" void kernel_launch(void* const* d_in, const int* in_sizes, int n_in,
                              void* d_out, int out_size)
{
    const float* x0 = (const float*)d_in[0];
    const float* x1 = (const float*)d_in[1];
    const float* x2 = (const float*)d_in[2];
    const float* qw = (const float*)d_in[3];
    const float* qb = (const float*)d_in[4];
    const float* kw = (const float*)d_in[5];
    const float* kb = (const float*)d_in[6];
    const float* vw = (const float*)d_in[7];
    const float* vb = (const float*)d_in[8];
    const float* cw = (const float*)d_in[9];
    const float* cb = (const float*)d_in[10];
    float* out = (float*)d_out;

    proj_kernel<<<dim3(T_/48, BH_, 5), 256>>>(x0, x1, x2, qw, qb, kw, kb, vw, vb);

    size_t smem = (size_t)SMEM_FLOATS * sizeof(float);
    cudaFuncSetAttribute(attn_kernel, cudaFuncAttributeMaxDynamicSharedMemorySize, (int)smem);
    attn_kernel<<<dim3(T_/ITILE_, BH_), 256, smem>>>();

    outproj_kernel<<<dim3((B_*T_)/8, C_/128), 256>>>(cw, cb, out);
}